// round 15
// baseline (speedup 1.0000x reference)
#include <cuda_runtime.h>
#include <stdint.h>
#include <math.h>

#define L_    2048
#define HID_  1024
#define H_    16
#define DH_   64
#define QS_   1024
#define T3_   3072
#define NCH_  32          // chunks of 64
#define EPS_  1.1920929e-07f

// ---------------- scratch (device globals; no allocation allowed) ----------------
__device__ float g_qkv[L_ * T3_];          // (L, 3072)
__device__ float g_dt[H_ * L_];
__device__ float g_Adec[H_ * L_];
__device__ float g_ca[H_ * L_];            // cumsum of A per head
__device__ float g_attn[L_ * QS_];         // (L, H*DH) post-RMSNorm
__device__ float g_pacc[L_ * QS_];         // intra-chunk partial accO (pre-RMSNorm)
__device__ float g_M[H_ * NCH_ * DH_ * DH_];      // per-chunk decayed outer products [e][d]
__device__ float g_state[H_ * NCH_ * DH_ * DH_];  // scanned states [e][d]

// =================================================================================
// tf32 mma.sync helpers
// =================================================================================
#define MMA_TF32(D, Ar, Br)                                                        \
    asm volatile("mma.sync.aligned.m16n8k8.row.col.f32.tf32.tf32.f32 "             \
                 "{%0,%1,%2,%3}, {%4,%5,%6,%7}, {%8,%9}, {%0,%1,%2,%3};"           \
                 : "+f"((D)[0]), "+f"((D)[1]), "+f"((D)[2]), "+f"((D)[3])          \
                 : "r"((Ar)[0]), "r"((Ar)[1]), "r"((Ar)[2]), "r"((Ar)[3]),         \
                   "r"((Br)[0]), "r"((Br)[1]))

__device__ __forceinline__ uint32_t f2tf32(float x) {
    uint32_t u;
    asm("cvt.rna.tf32.f32 %0, %1;" : "=r"(u) : "f"(x));
    return u;
}
__device__ __forceinline__ float f2tf32f(float x) { return __uint_as_float(f2tf32(x)); }

template <int STRIDE>
__device__ __forceinline__ void cvt_store(float* dst, int row, int cg, float4 x) {
    float4 y;
    y.x = f2tf32f(x.x);
    y.y = f2tf32f(x.y);
    y.z = f2tf32f(x.z);
    y.w = f2tf32f(x.w);
    *reinterpret_cast<float4*>(&dst[row * STRIDE + cg]) = y;
}

// K=2 causal depthwise conv on a float4 channel group: prev*w0 + cur*w1 + b
__device__ __forceinline__ float4 conv4(float4 cur, float4 prev,
                                        float4 wa, float4 wb, float4 bb) {
    float4 o;
    o.x = fmaf(cur.x, wa.y, fmaf(prev.x, wa.x, bb.x));
    o.y = fmaf(cur.y, wa.w, fmaf(prev.y, wa.z, bb.y));
    o.z = fmaf(cur.z, wb.y, fmaf(prev.z, wb.x, bb.z));
    o.w = fmaf(cur.w, wb.w, fmaf(prev.w, wb.z, bb.w));
    return o;
}

// =================================================================================
// TN GEMM on tensor pipe: CTA tile 128 x NT, K-step 32, double-buffered dyn smem.
// =================================================================================
template <int M, int N, int K, int NT>
__device__ __forceinline__ void mma_gemm_body(const float* __restrict__ A,
                                              const float* __restrict__ B,
                                              float* __restrict__ C)
{
    constexpr int NTN = NT / 16;
    constexpr int BNV = NT / 32;
    constexpr int GSA = 128 * 36;
    constexpr int GSB = NT * 36;
    constexpr int SS  = GSA + GSB;

    extern __shared__ __align__(16) float smem_g[];

    const int tid  = threadIdx.x;
    const int lane = tid & 31;
    const int wid  = tid >> 5;
    const int g    = lane >> 2;
    const int t4   = lane & 3;
    const int m0   = blockIdx.y * 128;
    const int n0   = blockIdx.x * NT;
    const int wm   = (wid >> 1) * 32;
    const int wn   = (wid & 1) * (NT / 2);

    int ar[4], ac[4];
#pragma unroll
    for (int r = 0; r < 4; r++) {
        const int v = tid + 256 * r;
        ar[r] = v >> 3;
        ac[r] = (v & 7) << 2;
    }
    int br_[BNV], bc_[BNV];
#pragma unroll
    for (int r = 0; r < BNV; r++) {
        const int v = tid + 256 * r;
        br_[r] = v >> 3;
        bc_[r] = (v & 7) << 2;
    }

    float acc[2][NTN][4];
#pragma unroll
    for (int mt = 0; mt < 2; mt++)
#pragma unroll
        for (int nt = 0; nt < NTN; nt++)
#pragma unroll
            for (int e = 0; e < 4; e++) acc[mt][nt][e] = 0.f;

#pragma unroll
    for (int r = 0; r < 4; r++)
        cvt_store<36>(smem_g, ar[r], ac[r],
            *reinterpret_cast<const float4*>(&A[(size_t)(m0 + ar[r]) * K + ac[r]]));
#pragma unroll
    for (int r = 0; r < BNV; r++)
        cvt_store<36>(smem_g + GSA, br_[r], bc_[r],
            *reinterpret_cast<const float4*>(&B[(size_t)(n0 + br_[r]) * K + bc_[r]]));
    __syncthreads();

    int buf = 0;
    for (int k0 = 0; k0 < K; k0 += 32) {
        const bool has_next = (k0 + 32) < K;
        const int kn = k0 + 32;
        const uint32_t* Au = reinterpret_cast<const uint32_t*>(smem_g + buf * SS);
        const uint32_t* Bu = reinterpret_cast<const uint32_t*>(smem_g + buf * SS + GSA);
        float* Asn = smem_g + (buf ^ 1) * SS;
        float* Bsn = smem_g + (buf ^ 1) * SS + GSA;

#pragma unroll
        for (int half = 0; half < 2; half++) {
            const int b_lo = (BNV * half) / 2;
            const int b_hi = (BNV * (half + 1)) / 2;

            float4 pa[2], pb[2];
            if (has_next) {
#pragma unroll
                for (int r = 0; r < 2; r++) {
                    const int i = half * 2 + r;
                    pa[r] = *reinterpret_cast<const float4*>(&A[(size_t)(m0 + ar[i]) * K + kn + ac[i]]);
                }
#pragma unroll
                for (int r = b_lo; r < b_hi; r++)
                    pb[r - b_lo] = *reinterpret_cast<const float4*>(&B[(size_t)(n0 + br_[r]) * K + kn + bc_[r]]);
            }

#pragma unroll
            for (int s = 0; s < 2; s++) {
                const int ks = half * 16 + s * 8;
                uint32_t a[2][4];
#pragma unroll
                for (int mt = 0; mt < 2; mt++) {
                    const int r = wm + mt * 16 + g;
                    a[mt][0] = Au[r * 36 + ks + t4];
                    a[mt][1] = Au[(r + 8) * 36 + ks + t4];
                    a[mt][2] = Au[r * 36 + ks + t4 + 4];
                    a[mt][3] = Au[(r + 8) * 36 + ks + t4 + 4];
                }
#pragma unroll
                for (int grp = 0; grp < NTN / 2; grp++) {
                    uint32_t b[2][2];
#pragma unroll
                    for (int q = 0; q < 2; q++) {
                        const int r = wn + (grp * 2 + q) * 8 + g;
                        b[q][0] = Bu[r * 36 + ks + t4];
                        b[q][1] = Bu[r * 36 + ks + t4 + 4];
                    }
#pragma unroll
                    for (int mt = 0; mt < 2; mt++)
#pragma unroll
                        for (int q = 0; q < 2; q++)
                            MMA_TF32(acc[mt][grp * 2 + q], a[mt], b[q]);
                }
            }

            if (has_next) {
#pragma unroll
                for (int r = 0; r < 2; r++) {
                    const int i = half * 2 + r;
                    cvt_store<36>(Asn, ar[i], ac[i], pa[r]);
                }
#pragma unroll
                for (int r = b_lo; r < b_hi; r++)
                    cvt_store<36>(Bsn, br_[r], bc_[r], pb[r - b_lo]);
            }
        }

        if (has_next) {
            __syncthreads();
            buf ^= 1;
        }
    }

#pragma unroll
    for (int mt = 0; mt < 2; mt++) {
#pragma unroll
        for (int nt = 0; nt < NTN; nt++) {
            const int row = m0 + wm + mt * 16 + g;
            const int col = n0 + wn + nt * 8 + t4 * 2;
            *reinterpret_cast<float2*>(&C[(size_t)row * N + col]) =
                make_float2(acc[mt][nt][0], acc[mt][nt][1]);
            *reinterpret_cast<float2*>(&C[(size_t)(row + 8) * N + col]) =
                make_float2(acc[mt][nt][2], acc[mt][nt][3]);
        }
    }
}

__global__ __launch_bounds__(256, 2) void mma_qkv_kernel(const float* __restrict__ X,
                                                         const float* __restrict__ W)
{
    mma_gemm_body<L_, T3_, HID_, 96>(X, W, g_qkv);
}

__global__ __launch_bounds__(256, 2) void mma_o_kernel(const float* __restrict__ W,
                                                       float* __restrict__ out)
{
    mma_gemm_body<L_, HID_, QS_, 64>(g_attn, W, out);
}

// ---------------- dt = softplus(X @ Wdt^T + b + dt_bias); A = -exp(A_log)*dt -----
__global__ __launch_bounds__(512) void dt_kernel(const float* __restrict__ X,
                                                 const float* __restrict__ W,
                                                 const float* __restrict__ b,
                                                 const float* __restrict__ dt_bias,
                                                 const float* __restrict__ A_log)
{
    const int l0 = blockIdx.x * 8;
    const int warp = threadIdx.x >> 5;   // head
    const int lane = threadIdx.x & 31;
    const float* w = W + (size_t)warp * HID_;

    float wreg[32];
#pragma unroll
    for (int j = 0; j < 32; j++) wreg[j] = w[lane + 32 * j];

    const float bb = b[warp] + dt_bias[warp];
    const float nA = -expf(A_log[warp]);

    for (int r = 0; r < 8; r++) {
        const int l = l0 + r;
        const float* x = X + (size_t)l * HID_;
        float s = 0.f;
#pragma unroll
        for (int j = 0; j < 32; j++) s = fmaf(x[lane + 32 * j], wreg[j], s);
#pragma unroll
        for (int o = 16; o; o >>= 1) s += __shfl_xor_sync(0xffffffffu, s, o);
        if (lane == 0) {
            float xv = s + bb;
            float dt = (xv > 20.f) ? xv : log1pf(expf(xv));
            g_dt[warp * L_ + l]   = dt;
            g_Adec[warp * L_ + l] = nA * dt;
        }
    }
}

// ---------------- per-head inclusive cumsum over L -------------------------------
__global__ __launch_bounds__(256) void cumsum_kernel()
{
    const int h = blockIdx.x;
    __shared__ float wsum[8];
    __shared__ float carry_s;
    const int tid = threadIdx.x, lane = tid & 31, warp = tid >> 5;
    if (tid == 0) carry_s = 0.f;
    __syncthreads();
    for (int base = 0; base < L_; base += 256) {
        float x = g_Adec[h * L_ + base + tid];
#pragma unroll
        for (int o = 1; o < 32; o <<= 1) {
            float t = __shfl_up_sync(0xffffffffu, x, o);
            if (lane >= o) x += t;
        }
        if (lane == 31) wsum[warp] = x;
        __syncthreads();
        if (tid < 8) {
            float w = wsum[tid];
#pragma unroll
            for (int o = 1; o < 8; o <<= 1) {
                float t = __shfl_up_sync(0xffu, w, o);
                if (tid >= o) w += t;
            }
            wsum[tid] = w;
        }
        __syncthreads();
        float pre = (warp > 0 ? wsum[warp - 1] : 0.f) + carry_s;
        float outv = x + pre;
        g_ca[h * L_ + base + tid] = outv;
        __syncthreads();
        if (tid == 255) carry_s = outv;
        __syncthreads();
    }
}

// =================================================================================
// Chunked linear attention — conv fused; coalesced staging; intra/inter split
// =================================================================================
#define AT_NW 68

// ---- Phase A: M'[e][d] = sum_m v[m,e]*k'[m,d], conv inline, coalesced loads -----
__global__ __launch_bounds__(128) void kv_outer_kernel(const float* __restrict__ kcw,
                                                       const float* __restrict__ kcb,
                                                       const float* __restrict__ vcw,
                                                       const float* __restrict__ vcb)
{
    __shared__ __align__(16) float Kt[64 * AT_NW];   // [d][m]
    __shared__ __align__(16) float Vt2[64 * AT_NW];  // [e][m]

    const int c = blockIdx.x, h = blockIdx.y;
    const int m0 = c * 64;
    const int tid = threadIdx.x, lane = tid & 31, w = tid >> 5;
    const int g = lane >> 2, t4 = lane & 3;
    const int wl = w * 16;
    const float* ca = g_ca + h * L_;
    const float bnext = ca[(c + 1) * 64];
    const float4 z = make_float4(0.f, 0.f, 0.f, 0.f);

    const int c4i = (tid & 15) << 2;
    const int ch = h * 64 + c4i;
    {
        const float4 kwa = *reinterpret_cast<const float4*>(&kcw[2 * ch]);
        const float4 kwb = *reinterpret_cast<const float4*>(&kcw[2 * ch + 4]);
        const float4 kbb = *reinterpret_cast<const float4*>(&kcb[ch]);
        const float4 vwa = *reinterpret_cast<const float4*>(&vcw[2 * ch]);
        const float4 vwb = *reinterpret_cast<const float4*>(&vcw[2 * ch + 4]);
        const float4 vbb = *reinterpret_cast<const float4*>(&vcb[ch]);
#pragma unroll
        for (int it = 0; it < 8; it++) {
            const int m = (tid >> 4) + it * 8;
            const int gm = m0 + m;
            const float wm = __expf(bnext - ca[gm]);
            const float dtv = g_dt[h * L_ + gm];
            const float* rowp  = g_qkv + (size_t)gm * T3_;
            const float* prowp = rowp - T3_;
            const bool hasp = (gm > 0);

            float4 kc4 = *reinterpret_cast<const float4*>(&rowp[QS_ + ch]);
            float4 kp4 = hasp ? *reinterpret_cast<const float4*>(&prowp[QS_ + ch]) : z;
            float4 vc4 = *reinterpret_cast<const float4*>(&rowp[2 * QS_ + ch]);
            float4 vp4 = hasp ? *reinterpret_cast<const float4*>(&prowp[2 * QS_ + ch]) : z;

            float4 kx = conv4(kc4, kp4, kwa, kwb, kbb);
            float4 vx = conv4(vc4, vp4, vwa, vwb, vbb);

            Kt[(c4i + 0) * AT_NW + m] = f2tf32f(kx.x * wm);
            Kt[(c4i + 1) * AT_NW + m] = f2tf32f(kx.y * wm);
            Kt[(c4i + 2) * AT_NW + m] = f2tf32f(kx.z * wm);
            Kt[(c4i + 3) * AT_NW + m] = f2tf32f(kx.w * wm);
            Vt2[(c4i + 0) * AT_NW + m] = f2tf32f(vx.x * dtv);
            Vt2[(c4i + 1) * AT_NW + m] = f2tf32f(vx.y * dtv);
            Vt2[(c4i + 2) * AT_NW + m] = f2tf32f(vx.z * dtv);
            Vt2[(c4i + 3) * AT_NW + m] = f2tf32f(vx.w * dtv);
        }
    }
    __syncthreads();

    float acc[8][4];
#pragma unroll
    for (int nt = 0; nt < 8; nt++)
#pragma unroll
        for (int e = 0; e < 4; e++) acc[nt][e] = 0.f;

    const uint32_t* Vu = reinterpret_cast<const uint32_t*>(Vt2);
    const uint32_t* Ku = reinterpret_cast<const uint32_t*>(Kt);
#pragma unroll
    for (int ko = 0; ko < 8; ko++) {
        uint32_t a[4];
        a[0] = Vu[(wl + g) * AT_NW + ko * 8 + t4];
        a[1] = Vu[(wl + g + 8) * AT_NW + ko * 8 + t4];
        a[2] = Vu[(wl + g) * AT_NW + ko * 8 + t4 + 4];
        a[3] = Vu[(wl + g + 8) * AT_NW + ko * 8 + t4 + 4];
#pragma unroll
        for (int nt = 0; nt < 8; nt++) {
            uint32_t b[2];
            b[0] = Ku[(nt * 8 + g) * AT_NW + ko * 8 + t4];
            b[1] = Ku[(nt * 8 + g) * AT_NW + ko * 8 + t4 + 4];
            MMA_TF32(acc[nt], a, b);
        }
    }

    float* Md = g_M + ((size_t)(h * NCH_ + c) << 12);
#pragma unroll
    for (int nt = 0; nt < 8; nt++) {
        const int dc = nt * 8 + 2 * t4;
        *reinterpret_cast<float2*>(&Md[(wl + g) * 64 + dc])     = make_float2(acc[nt][0], acc[nt][1]);
        *reinterpret_cast<float2*>(&Md[(wl + g + 8) * 64 + dc]) = make_float2(acc[nt][2], acc[nt][3]);
    }
}

// ---- Phase B: per-head state scan, depth-2 register prefetch. grid H, 1024 thr --
__global__ __launch_bounds__(1024) void state_scan_kernel()
{
    const int h = blockIdx.x, t = threadIdx.x;
    __shared__ float decs[NCH_];
    if (t < NCH_) {
        const float* ca = g_ca + h * L_;
        decs[t] = (t < NCH_ - 1) ? __expf(ca[(t + 1) * 64] - ca[t * 64]) : 0.f;
    }
    __syncthreads();

    const float* Mbase = g_M + ((size_t)h * NCH_ << 12);
    float* Sbase = g_state + ((size_t)h * NCH_ << 12);
    const int off = t * 4;

    float4 st = make_float4(0.f, 0.f, 0.f, 0.f);
    float4 mbuf0 = *reinterpret_cast<const float4*>(&Mbase[off]);
    float4 mbuf1 = *reinterpret_cast<const float4*>(&Mbase[(1 << 12) + off]);

    for (int c = 0; c < NCH_; c++) {
        *reinterpret_cast<float4*>(&Sbase[((size_t)c << 12) + off]) = st;
        if (c < NCH_ - 1) {
            const float dec = decs[c];
            st.x = fmaf(st.x, dec, mbuf0.x);
            st.y = fmaf(st.y, dec, mbuf0.y);
            st.z = fmaf(st.z, dec, mbuf0.z);
            st.w = fmaf(st.w, dec, mbuf0.w);
            mbuf0 = mbuf1;
            if (c + 2 < NCH_)
                mbuf1 = *reinterpret_cast<const float4*>(&Mbase[((size_t)(c + 2) << 12) + off]);
        }
    }
}

// ---- Phase C1 (intra): diagonal tile only, conv fused -> g_pacc (pre-RMS) -------
__global__ __launch_bounds__(128) void attn_intra_kernel(const float* __restrict__ order_coeff,
                                                         const float* __restrict__ qcw,
                                                         const float* __restrict__ qcb,
                                                         const float* __restrict__ kcw,
                                                         const float* __restrict__ kcb,
                                                         const float* __restrict__ vcw,
                                                         const float* __restrict__ vcb)
{
    __shared__ __align__(16) float KSs[64 * AT_NW];   // Q staging -> K -> weighted S
    __shared__ __align__(16) float Vt[64 * AT_NW];    // V^T

    const int h    = blockIdx.y;
    const int lt   = blockIdx.x;
    const int l0   = lt * 64;
    const int tid  = threadIdx.x;
    const int lane = tid & 31;
    const int w    = tid >> 5;
    const int g    = lane >> 2;
    const int t4   = lane & 3;
    const int wl   = w * 16;

    const float* ca = g_ca + h * L_;
    const float lc  = __logf(1.f / order_coeff[h]);
    const float4 z = make_float4(0.f, 0.f, 0.f, 0.f);

    const int c4i = (tid & 15) << 2;
    const int chq = h * 64 + c4i;

    // ---- stage Q (conv fused, tf32) into KSs ----
    {
        const float4 qwa = *reinterpret_cast<const float4*>(&qcw[2 * chq]);
        const float4 qwb = *reinterpret_cast<const float4*>(&qcw[2 * chq + 4]);
        const float4 qbb = *reinterpret_cast<const float4*>(&qcb[chq]);
#pragma unroll
        for (int it = 0; it < 8; it++) {
            const int row = (tid >> 4) + it * 8;
            const int gl = l0 + row;
            float4 qc4 = *reinterpret_cast<const float4*>(&g_qkv[(size_t)gl * T3_ + chq]);
            float4 qp4 = (gl > 0) ? *reinterpret_cast<const float4*>(&g_qkv[(size_t)(gl - 1) * T3_ + chq]) : z;
            cvt_store<AT_NW>(KSs, row, c4i, conv4(qc4, qp4, qwa, qwb, qbb));
        }
    }
    __syncthreads();

    uint32_t qa[8][4];
    {
        const uint32_t* Qu = reinterpret_cast<const uint32_t*>(KSs);
#pragma unroll
        for (int ko = 0; ko < 8; ko++) {
            qa[ko][0] = Qu[(wl + g) * AT_NW + ko * 8 + t4];
            qa[ko][1] = Qu[(wl + g + 8) * AT_NW + ko * 8 + t4];
            qa[ko][2] = Qu[(wl + g) * AT_NW + ko * 8 + t4 + 4];
            qa[ko][3] = Qu[(wl + g + 8) * AT_NW + ko * 8 + t4 + 4];
        }
    }
    const float cl0 = ca[l0 + wl + g] + lc;
    const float cl1 = ca[l0 + wl + g + 8] + lc;
    __syncthreads();

    // ---- load K (conv fused) into KSs row-major; V (conv fused, *dt) into Vt^T ----
    {
        const float4 kwa = *reinterpret_cast<const float4*>(&kcw[2 * chq]);
        const float4 kwb = *reinterpret_cast<const float4*>(&kcw[2 * chq + 4]);
        const float4 kbb = *reinterpret_cast<const float4*>(&kcb[chq]);
        const float4 vwa = *reinterpret_cast<const float4*>(&vcw[2 * chq]);
        const float4 vwb = *reinterpret_cast<const float4*>(&vcw[2 * chq + 4]);
        const float4 vbb = *reinterpret_cast<const float4*>(&vcb[chq]);
#pragma unroll
        for (int it = 0; it < 8; it++) {
            const int row = (tid >> 4) + it * 8;
            const int gl = l0 + row;
            const float dtv = g_dt[h * L_ + gl];
            const float* rowp  = g_qkv + (size_t)gl * T3_;
            const float* prowp = rowp - T3_;
            const bool hasp = (gl > 0);
            float4 kc4 = *reinterpret_cast<const float4*>(&rowp[QS_ + chq]);
            float4 kp4 = hasp ? *reinterpret_cast<const float4*>(&prowp[QS_ + chq]) : z;
            cvt_store<AT_NW>(KSs, row, c4i, conv4(kc4, kp4, kwa, kwb, kbb));

            float4 vc4 = *reinterpret_cast<const float4*>(&rowp[2 * QS_ + chq]);
            float4 vp4 = hasp ? *reinterpret_cast<const float4*>(&prowp[2 * QS_ + chq]) : z;
            float4 vx = conv4(vc4, vp4, vwa, vwb, vbb);
            Vt[(c4i + 0) * AT_NW + row] = f2tf32f(vx.x * dtv);
            Vt[(c4i + 1) * AT_NW + row] = f2tf32f(vx.y * dtv);
            Vt[(c4i + 2) * AT_NW + row] = f2tf32f(vx.z * dtv);
            Vt[(c4i + 3) * AT_NW + row] = f2tf32f(vx.w * dtv);
        }
    }
    __syncthreads();

    // S-phase
    float sfr[8][4];
#pragma unroll
    for (int nt = 0; nt < 8; nt++)
#pragma unroll
        for (int e = 0; e < 4; e++) sfr[nt][e] = 0.f;

    {
        const uint32_t* Ku = reinterpret_cast<const uint32_t*>(KSs);
#pragma unroll
        for (int ko = 0; ko < 8; ko++) {
            uint32_t b[8][2];
#pragma unroll
            for (int nt = 0; nt < 8; nt++) {
                b[nt][0] = Ku[(nt * 8 + g) * AT_NW + ko * 8 + t4];
                b[nt][1] = Ku[(nt * 8 + g) * AT_NW + ko * 8 + t4 + 4];
            }
#pragma unroll
            for (int nt = 0; nt < 8; nt++)
                MMA_TF32(sfr[nt], qa[ko], b[nt]);
        }
    }

    const int gl0 = l0 + wl + g, gl1 = gl0 + 8;
#pragma unroll
    for (int nt = 0; nt < 8; nt++) {
        const int gm0 = l0 + nt * 8 + 2 * t4;
        const int gm1 = gm0 + 1;
        const float cm0 = ca[gm0], cm1 = ca[gm1];
        sfr[nt][0] *= (gm0 <= gl0) ? __expf(cl0 - cm0) : 0.f;
        sfr[nt][1] *= (gm1 <= gl0) ? __expf(cl0 - cm1) : 0.f;
        sfr[nt][2] *= (gm0 <= gl1) ? __expf(cl1 - cm0) : 0.f;
        sfr[nt][3] *= (gm1 <= gl1) ? __expf(cl1 - cm1) : 0.f;
    }
    __syncthreads();

#pragma unroll
    for (int nt = 0; nt < 8; nt++) {
        const int cc = nt * 8 + 2 * t4;
        *reinterpret_cast<float2*>(&KSs[(wl + g) * AT_NW + cc]) =
            make_float2(f2tf32f(sfr[nt][0]), f2tf32f(sfr[nt][1]));
        *reinterpret_cast<float2*>(&KSs[(wl + g + 8) * AT_NW + cc]) =
            make_float2(f2tf32f(sfr[nt][2]), f2tf32f(sfr[nt][3]));
    }
    __syncwarp();

    float accO[8][4];
#pragma unroll
    for (int nt = 0; nt < 8; nt++)
#pragma unroll
        for (int e = 0; e < 4; e++) accO[nt][e] = 0.f;

    {
        const uint32_t* Su = reinterpret_cast<const uint32_t*>(KSs);
        const uint32_t* Vu = reinterpret_cast<const uint32_t*>(Vt);
#pragma unroll
        for (int ko = 0; ko < 8; ko++) {
            uint32_t a[4];
            a[0] = Su[(wl + g) * AT_NW + ko * 8 + t4];
            a[1] = Su[(wl + g + 8) * AT_NW + ko * 8 + t4];
            a[2] = Su[(wl + g) * AT_NW + ko * 8 + t4 + 4];
            a[3] = Su[(wl + g + 8) * AT_NW + ko * 8 + t4 + 4];
#pragma unroll
            for (int nt = 0; nt < 8; nt++) {
                uint32_t b[2];
                b[0] = Vu[(nt * 8 + g) * AT_NW + ko * 8 + t4];
                b[1] = Vu[(nt * 8 + g) * AT_NW + ko * 8 + t4 + 4];
                MMA_TF32(accO[nt], a, b);
            }
        }
    }

    // write pre-RMS partial
#pragma unroll
    for (int nt = 0; nt < 8; nt++) {
        const int dc = nt * 8 + 2 * t4;
        const int col = h * DH_ + dc;
        *reinterpret_cast<float2*>(&g_pacc[(size_t)(l0 + wl + g) * QS_ + col]) =
            make_float2(accO[nt][0], accO[nt][1]);
        *reinterpret_cast<float2*>(&g_pacc[(size_t)(l0 + wl + g + 8) * QS_ + col]) =
            make_float2(accO[nt][2], accO[nt][3]);
    }
}

// ---- Phase C2 (inter): P = Q.State^T * iw + partial, RMSNorm, write g_attn ------
__global__ __launch_bounds__(128) void attn_inter_kernel(const float* __restrict__ norm_w,
                                                         const float* __restrict__ order_coeff,
                                                         const float* __restrict__ qcw,
                                                         const float* __restrict__ qcb)
{
    __shared__ __align__(16) float Qs[64 * AT_NW];
    __shared__ __align__(16) float St[64 * AT_NW];

    const int h    = blockIdx.y;
    const int lt   = blockIdx.x;
    const int l0   = lt * 64;
    const int tid  = threadIdx.x;
    const int lane = tid & 31;
    const int w    = tid >> 5;
    const int g    = lane >> 2;
    const int t4   = lane & 3;
    const int wl   = w * 16;

    const float* ca = g_ca + h * L_;
    const float lc  = __logf(1.f / order_coeff[h]);
    const float4 z = make_float4(0.f, 0.f, 0.f, 0.f);

    const int c4i = (tid & 15) << 2;
    const int chq = h * 64 + c4i;

    // stage Q (conv fused, tf32) and State
    {
        const float4 qwa = *reinterpret_cast<const float4*>(&qcw[2 * chq]);
        const float4 qwb = *reinterpret_cast<const float4*>(&qcw[2 * chq + 4]);
        const float4 qbb = *reinterpret_cast<const float4*>(&qcb[chq]);
        const float* Sg = g_state + ((size_t)(h * NCH_ + lt) << 12);
#pragma unroll
        for (int it = 0; it < 8; it++) {
            const int row = (tid >> 4) + it * 8;
            const int gl = l0 + row;
            float4 qc4 = *reinterpret_cast<const float4*>(&g_qkv[(size_t)gl * T3_ + chq]);
            float4 qp4 = (gl > 0) ? *reinterpret_cast<const float4*>(&g_qkv[(size_t)(gl - 1) * T3_ + chq]) : z;
            cvt_store<AT_NW>(Qs, row, c4i, conv4(qc4, qp4, qwa, qwb, qbb));
            cvt_store<AT_NW>(St, row, c4i,
                *reinterpret_cast<const float4*>(&Sg[row * 64 + c4i]));
        }
    }
    __syncthreads();

    uint32_t qa[8][4];
    {
        const uint32_t* Qu = reinterpret_cast<const uint32_t*>(Qs);
#pragma unroll
        for (int ko = 0; ko < 8; ko++) {
            qa[ko][0] = Qu[(wl + g) * AT_NW + ko * 8 + t4];
            qa[ko][1] = Qu[(wl + g + 8) * AT_NW + ko * 8 + t4];
            qa[ko][2] = Qu[(wl + g) * AT_NW + ko * 8 + t4 + 4];
            qa[ko][3] = Qu[(wl + g + 8) * AT_NW + ko * 8 + t4 + 4];
        }
    }
    const float cl0 = ca[l0 + wl + g] + lc;
    const float cl1 = ca[l0 + wl + g + 8] + lc;
    const float bc  = ca[l0];
    const float iw0 = __expf(cl0 - bc);
    const float iw1 = __expf(cl1 - bc);

    float accO[8][4];
#pragma unroll
    for (int nt = 0; nt < 8; nt++)
#pragma unroll
        for (int e = 0; e < 4; e++) accO[nt][e] = 0.f;

    {
        const uint32_t* Su = reinterpret_cast<const uint32_t*>(St);
#pragma unroll
        for (int ko = 0; ko < 8; ko++) {
            uint32_t b[8][2];
#pragma unroll
            for (int nt = 0; nt < 8; nt++) {
                b[nt][0] = Su[(nt * 8 + g) * AT_NW + ko * 8 + t4];
                b[nt][1] = Su[(nt * 8 + g) * AT_NW + ko * 8 + t4 + 4];
            }
#pragma unroll
            for (int nt = 0; nt < 8; nt++)
                MMA_TF32(accO[nt], qa[ko], b[nt]);
        }
    }

    // add intra partial
#pragma unroll
    for (int nt = 0; nt < 8; nt++) {
        const int dc = nt * 8 + 2 * t4;
        const int col = h * DH_ + dc;
        const float2 p0 = *reinterpret_cast<const float2*>(&g_pacc[(size_t)(l0 + wl + g) * QS_ + col]);
        const float2 p1 = *reinterpret_cast<const float2*>(&g_pacc[(size_t)(l0 + wl + g + 8) * QS_ + col]);
        accO[nt][0] = fmaf(accO[nt][0], iw0, p0.x);
        accO[nt][1] = fmaf(accO[nt][1], iw0, p0.y);
        accO[nt][2] = fmaf(accO[nt][2], iw1, p1.x);
        accO[nt][3] = fmaf(accO[nt][3], iw1, p1.y);
    }

    // RMSNorm + write
    float ss0 = 0.f, ss1 = 0.f;
#pragma unroll
    for (int nt = 0; nt < 8; nt++) {
        ss0 = fmaf(accO[nt][0], accO[nt][0], ss0);
        ss0 = fmaf(accO[nt][1], accO[nt][1], ss0);
        ss1 = fmaf(accO[nt][2], accO[nt][2], ss1);
        ss1 = fmaf(accO[nt][3], accO[nt][3], ss1);
    }
    ss0 += __shfl_xor_sync(0xffffffffu, ss0, 1);
    ss0 += __shfl_xor_sync(0xffffffffu, ss0, 2);
    ss1 += __shfl_xor_sync(0xffffffffu, ss1, 1);
    ss1 += __shfl_xor_sync(0xffffffffu, ss1, 2);
    const float r0 = rsqrtf(ss0 * (1.f / 64.f) + EPS_);
    const float r1 = rsqrtf(ss1 * (1.f / 64.f) + EPS_);

#pragma unroll
    for (int nt = 0; nt < 8; nt++) {
        const int dc = nt * 8 + 2 * t4;
        const float2 nw = *reinterpret_cast<const float2*>(&norm_w[dc]);
        const int col = h * DH_ + dc;
        *reinterpret_cast<float2*>(&g_attn[(size_t)(l0 + wl + g) * QS_ + col]) =
            make_float2(accO[nt][0] * r0 * nw.x, accO[nt][1] * r0 * nw.y);
        *reinterpret_cast<float2*>(&g_attn[(size_t)(l0 + wl + g + 8) * QS_ + col]) =
            make_float2(accO[nt][2] * r1 * nw.x, accO[nt][3] * r1 * nw.y);
    }
}

// ---------------- launch ---------------------------------------------------------
#define GEMM_SMEM_QKV ((128 + 96) * 36 * 2 * (int)sizeof(float))   // 64512 bytes
#define GEMM_SMEM_O   ((128 + 64) * 36 * 2 * (int)sizeof(float))   // 55296 bytes

extern "C" void kernel_launch(void* const* d_in, const int* in_sizes, int n_in,
                              void* d_out, int out_size)
{
    const float* hidden    = (const float*)d_in[0];
    // d_in[1] = attention_mask (causal triu) — structurally known, unused
    const float* qkv_w     = (const float*)d_in[2];
    const float* q_conv_w  = (const float*)d_in[3];
    const float* q_conv_b  = (const float*)d_in[4];
    const float* k_conv_w  = (const float*)d_in[5];
    const float* k_conv_b  = (const float*)d_in[6];
    const float* v_conv_w  = (const float*)d_in[7];
    const float* v_conv_b  = (const float*)d_in[8];
    const float* norm_w    = (const float*)d_in[9];
    const float* A_log     = (const float*)d_in[10];
    const float* dt_bias   = (const float*)d_in[11];
    const float* dt_proj_w = (const float*)d_in[12];
    const float* dt_proj_b = (const float*)d_in[13];
    const float* o_w       = (const float*)d_in[14];
    const float* order_c   = (const float*)d_in[15];
    float* out = (float*)d_out;

    static int init_done = 0;
    static cudaStream_t s2;
    static cudaEvent_t ev_fork, ev_dt, ev_qkv, ev_scan;
    if (!init_done) {
        cudaFuncSetAttribute(mma_qkv_kernel, cudaFuncAttributeMaxDynamicSharedMemorySize, GEMM_SMEM_QKV);
        cudaFuncSetAttribute(mma_o_kernel,   cudaFuncAttributeMaxDynamicSharedMemorySize, GEMM_SMEM_O);
        cudaStreamCreateWithFlags(&s2, cudaStreamNonBlocking);
        cudaEventCreateWithFlags(&ev_fork, cudaEventDisableTiming);
        cudaEventCreateWithFlags(&ev_dt,   cudaEventDisableTiming);
        cudaEventCreateWithFlags(&ev_qkv,  cudaEventDisableTiming);
        cudaEventCreateWithFlags(&ev_scan, cudaEventDisableTiming);
        init_done = 1;
    }

    // fork: dt + cumsum (depend only on hidden) concurrent with the qkv GEMM
    cudaEventRecord(ev_fork, 0);
    cudaStreamWaitEvent(s2, ev_fork, 0);
    dt_kernel<<<L_ / 8, 512, 0, s2>>>(hidden, dt_proj_w, dt_proj_b, dt_bias, A_log);
    cumsum_kernel<<<H_, 256, 0, s2>>>();
    cudaEventRecord(ev_dt, s2);

    mma_qkv_kernel<<<dim3(T3_ / 96, L_ / 128), 256, GEMM_SMEM_QKV>>>(hidden, qkv_w);
    cudaEventRecord(ev_qkv, 0);

    // s2: kv_outer -> scan  (needs qkv + dt/ca; dt/ca already in s2 order)
    cudaStreamWaitEvent(s2, ev_qkv, 0);
    kv_outer_kernel<<<dim3(NCH_ - 1, H_), 128, 0, s2>>>(k_conv_w, k_conv_b, v_conv_w, v_conv_b);
    state_scan_kernel<<<H_, 1024, 0, s2>>>();
    cudaEventRecord(ev_scan, s2);

    // main: intra attention overlaps with kv_outer/scan
    cudaStreamWaitEvent(0, ev_dt, 0);
    attn_intra_kernel<<<dim3(NCH_, H_), 128>>>(order_c,
                                               q_conv_w, q_conv_b, k_conv_w, k_conv_b,
                                               v_conv_w, v_conv_b);
    cudaStreamWaitEvent(0, ev_scan, 0);
    attn_inter_kernel<<<dim3(NCH_, H_), 128>>>(norm_w, order_c, q_conv_w, q_conv_b);
    mma_o_kernel<<<dim3(HID_ / 64, L_ / 128), 256, GEMM_SMEM_O>>>(o_w, out);
}

// round 16
// speedup vs baseline: 1.0221x; 1.0221x over previous
#include <cuda_runtime.h>
#include <stdint.h>
#include <math.h>

#define L_    2048
#define HID_  1024
#define H_    16
#define DH_   64
#define QS_   1024
#define T3_   3072
#define NCH_  32          // chunks of 64
#define EPS_  1.1920929e-07f

// ---------------- scratch (device globals; no allocation allowed) ----------------
__device__ float g_qkv[L_ * T3_];          // (L, 3072)
__device__ float g_dt[H_ * L_];
__device__ float g_Adec[H_ * L_];
__device__ float g_ca[H_ * L_];            // cumsum of A per head
__device__ float g_attn[L_ * QS_];         // (L, H*DH) post-RMSNorm
__device__ float g_pacc[L_ * QS_];         // intra-chunk partial accO (pre-RMSNorm)
__device__ float g_M[H_ * NCH_ * DH_ * DH_];      // per-chunk decayed outer products [e][d]
__device__ float g_state[H_ * NCH_ * DH_ * DH_];  // scanned states [e][d]

// =================================================================================
// tf32 mma.sync helpers
// =================================================================================
#define MMA_TF32(D, Ar, Br)                                                        \
    asm volatile("mma.sync.aligned.m16n8k8.row.col.f32.tf32.tf32.f32 "             \
                 "{%0,%1,%2,%3}, {%4,%5,%6,%7}, {%8,%9}, {%0,%1,%2,%3};"           \
                 : "+f"((D)[0]), "+f"((D)[1]), "+f"((D)[2]), "+f"((D)[3])          \
                 : "r"((Ar)[0]), "r"((Ar)[1]), "r"((Ar)[2]), "r"((Ar)[3]),         \
                   "r"((Br)[0]), "r"((Br)[1]))

__device__ __forceinline__ uint32_t f2tf32(float x) {
    uint32_t u;
    asm("cvt.rna.tf32.f32 %0, %1;" : "=r"(u) : "f"(x));
    return u;
}
__device__ __forceinline__ float f2tf32f(float x) { return __uint_as_float(f2tf32(x)); }

template <int STRIDE>
__device__ __forceinline__ void cvt_store(float* dst, int row, int cg, float4 x) {
    float4 y;
    y.x = f2tf32f(x.x);
    y.y = f2tf32f(x.y);
    y.z = f2tf32f(x.z);
    y.w = f2tf32f(x.w);
    *reinterpret_cast<float4*>(&dst[row * STRIDE + cg]) = y;
}

// K=2 causal depthwise conv on a float4 channel group: prev*w0 + cur*w1 + b
__device__ __forceinline__ float4 conv4(float4 cur, float4 prev,
                                        float4 wa, float4 wb, float4 bb) {
    float4 o;
    o.x = fmaf(cur.x, wa.y, fmaf(prev.x, wa.x, bb.x));
    o.y = fmaf(cur.y, wa.w, fmaf(prev.y, wa.z, bb.y));
    o.z = fmaf(cur.z, wb.y, fmaf(prev.z, wb.x, bb.z));
    o.w = fmaf(cur.w, wb.w, fmaf(prev.w, wb.z, bb.w));
    return o;
}

// =================================================================================
// TN GEMM on tensor pipe: CTA tile 128 x NT, K-step 32, double-buffered dyn smem.
// =================================================================================
template <int M, int N, int K, int NT>
__device__ __forceinline__ void mma_gemm_body(const float* __restrict__ A,
                                              const float* __restrict__ B,
                                              float* __restrict__ C)
{
    constexpr int NTN = NT / 16;
    constexpr int BNV = NT / 32;
    constexpr int GSA = 128 * 36;
    constexpr int GSB = NT * 36;
    constexpr int SS  = GSA + GSB;

    extern __shared__ __align__(16) float smem_g[];

    const int tid  = threadIdx.x;
    const int lane = tid & 31;
    const int wid  = tid >> 5;
    const int g    = lane >> 2;
    const int t4   = lane & 3;
    const int m0   = blockIdx.y * 128;
    const int n0   = blockIdx.x * NT;
    const int wm   = (wid >> 1) * 32;
    const int wn   = (wid & 1) * (NT / 2);

    int ar[4], ac[4];
#pragma unroll
    for (int r = 0; r < 4; r++) {
        const int v = tid + 256 * r;
        ar[r] = v >> 3;
        ac[r] = (v & 7) << 2;
    }
    int br_[BNV], bc_[BNV];
#pragma unroll
    for (int r = 0; r < BNV; r++) {
        const int v = tid + 256 * r;
        br_[r] = v >> 3;
        bc_[r] = (v & 7) << 2;
    }

    float acc[2][NTN][4];
#pragma unroll
    for (int mt = 0; mt < 2; mt++)
#pragma unroll
        for (int nt = 0; nt < NTN; nt++)
#pragma unroll
            for (int e = 0; e < 4; e++) acc[mt][nt][e] = 0.f;

#pragma unroll
    for (int r = 0; r < 4; r++)
        cvt_store<36>(smem_g, ar[r], ac[r],
            *reinterpret_cast<const float4*>(&A[(size_t)(m0 + ar[r]) * K + ac[r]]));
#pragma unroll
    for (int r = 0; r < BNV; r++)
        cvt_store<36>(smem_g + GSA, br_[r], bc_[r],
            *reinterpret_cast<const float4*>(&B[(size_t)(n0 + br_[r]) * K + bc_[r]]));
    __syncthreads();

    int buf = 0;
    for (int k0 = 0; k0 < K; k0 += 32) {
        const bool has_next = (k0 + 32) < K;
        const int kn = k0 + 32;
        const uint32_t* Au = reinterpret_cast<const uint32_t*>(smem_g + buf * SS);
        const uint32_t* Bu = reinterpret_cast<const uint32_t*>(smem_g + buf * SS + GSA);
        float* Asn = smem_g + (buf ^ 1) * SS;
        float* Bsn = smem_g + (buf ^ 1) * SS + GSA;

#pragma unroll
        for (int half = 0; half < 2; half++) {
            const int b_lo = (BNV * half) / 2;
            const int b_hi = (BNV * (half + 1)) / 2;

            float4 pa[2], pb[2];
            if (has_next) {
#pragma unroll
                for (int r = 0; r < 2; r++) {
                    const int i = half * 2 + r;
                    pa[r] = *reinterpret_cast<const float4*>(&A[(size_t)(m0 + ar[i]) * K + kn + ac[i]]);
                }
#pragma unroll
                for (int r = b_lo; r < b_hi; r++)
                    pb[r - b_lo] = *reinterpret_cast<const float4*>(&B[(size_t)(n0 + br_[r]) * K + kn + bc_[r]]);
            }

#pragma unroll
            for (int s = 0; s < 2; s++) {
                const int ks = half * 16 + s * 8;
                uint32_t a[2][4];
#pragma unroll
                for (int mt = 0; mt < 2; mt++) {
                    const int r = wm + mt * 16 + g;
                    a[mt][0] = Au[r * 36 + ks + t4];
                    a[mt][1] = Au[(r + 8) * 36 + ks + t4];
                    a[mt][2] = Au[r * 36 + ks + t4 + 4];
                    a[mt][3] = Au[(r + 8) * 36 + ks + t4 + 4];
                }
#pragma unroll
                for (int grp = 0; grp < NTN / 2; grp++) {
                    uint32_t b[2][2];
#pragma unroll
                    for (int q = 0; q < 2; q++) {
                        const int r = wn + (grp * 2 + q) * 8 + g;
                        b[q][0] = Bu[r * 36 + ks + t4];
                        b[q][1] = Bu[r * 36 + ks + t4 + 4];
                    }
#pragma unroll
                    for (int mt = 0; mt < 2; mt++)
#pragma unroll
                        for (int q = 0; q < 2; q++)
                            MMA_TF32(acc[mt][grp * 2 + q], a[mt], b[q]);
                }
            }

            if (has_next) {
#pragma unroll
                for (int r = 0; r < 2; r++) {
                    const int i = half * 2 + r;
                    cvt_store<36>(Asn, ar[i], ac[i], pa[r]);
                }
#pragma unroll
                for (int r = b_lo; r < b_hi; r++)
                    cvt_store<36>(Bsn, br_[r], bc_[r], pb[r - b_lo]);
            }
        }

        if (has_next) {
            __syncthreads();
            buf ^= 1;
        }
    }

#pragma unroll
    for (int mt = 0; mt < 2; mt++) {
#pragma unroll
        for (int nt = 0; nt < NTN; nt++) {
            const int row = m0 + wm + mt * 16 + g;
            const int col = n0 + wn + nt * 8 + t4 * 2;
            *reinterpret_cast<float2*>(&C[(size_t)row * N + col]) =
                make_float2(acc[mt][nt][0], acc[mt][nt][1]);
            *reinterpret_cast<float2*>(&C[(size_t)(row + 8) * N + col]) =
                make_float2(acc[mt][nt][2], acc[mt][nt][3]);
        }
    }
}

__global__ __launch_bounds__(256, 2) void mma_qkv_kernel(const float* __restrict__ X,
                                                         const float* __restrict__ W)
{
    mma_gemm_body<L_, T3_, HID_, 96>(X, W, g_qkv);
}

__global__ __launch_bounds__(256, 2) void mma_o_kernel(const float* __restrict__ W,
                                                       float* __restrict__ out)
{
    mma_gemm_body<L_, HID_, QS_, 64>(g_attn, W, out);
}

// ---------------- dt = softplus(X @ Wdt^T + b + dt_bias); A = -exp(A_log)*dt -----
__global__ __launch_bounds__(512) void dt_kernel(const float* __restrict__ X,
                                                 const float* __restrict__ W,
                                                 const float* __restrict__ b,
                                                 const float* __restrict__ dt_bias,
                                                 const float* __restrict__ A_log)
{
    const int l0 = blockIdx.x * 8;
    const int warp = threadIdx.x >> 5;   // head
    const int lane = threadIdx.x & 31;
    const float* w = W + (size_t)warp * HID_;

    float wreg[32];
#pragma unroll
    for (int j = 0; j < 32; j++) wreg[j] = w[lane + 32 * j];

    const float bb = b[warp] + dt_bias[warp];
    const float nA = -expf(A_log[warp]);

    for (int r = 0; r < 8; r++) {
        const int l = l0 + r;
        const float* x = X + (size_t)l * HID_;
        float s = 0.f;
#pragma unroll
        for (int j = 0; j < 32; j++) s = fmaf(x[lane + 32 * j], wreg[j], s);
#pragma unroll
        for (int o = 16; o; o >>= 1) s += __shfl_xor_sync(0xffffffffu, s, o);
        if (lane == 0) {
            float xv = s + bb;
            float dt = (xv > 20.f) ? xv : log1pf(expf(xv));
            g_dt[warp * L_ + l]   = dt;
            g_Adec[warp * L_ + l] = nA * dt;
        }
    }
}

// ---------------- per-head inclusive cumsum over L -------------------------------
__global__ __launch_bounds__(256) void cumsum_kernel()
{
    const int h = blockIdx.x;
    __shared__ float wsum[8];
    __shared__ float carry_s;
    const int tid = threadIdx.x, lane = tid & 31, warp = tid >> 5;
    if (tid == 0) carry_s = 0.f;
    __syncthreads();
    for (int base = 0; base < L_; base += 256) {
        float x = g_Adec[h * L_ + base + tid];
#pragma unroll
        for (int o = 1; o < 32; o <<= 1) {
            float t = __shfl_up_sync(0xffffffffu, x, o);
            if (lane >= o) x += t;
        }
        if (lane == 31) wsum[warp] = x;
        __syncthreads();
        if (tid < 8) {
            float w = wsum[tid];
#pragma unroll
            for (int o = 1; o < 8; o <<= 1) {
                float t = __shfl_up_sync(0xffu, w, o);
                if (tid >= o) w += t;
            }
            wsum[tid] = w;
        }
        __syncthreads();
        float pre = (warp > 0 ? wsum[warp - 1] : 0.f) + carry_s;
        float outv = x + pre;
        g_ca[h * L_ + base + tid] = outv;
        __syncthreads();
        if (tid == 255) carry_s = outv;
        __syncthreads();
    }
}

// =================================================================================
// Chunked linear attention — fused intra+M kernel; scan; inter kernel
// =================================================================================
#define AT_NW 68
#define ATTN_SMEM (3 * 64 * AT_NW * (int)sizeof(float))   // 52224 bytes

// ---- Fused: diagonal tile -> g_pacc AND decayed outer product M -> g_M ----------
// Shares the K/V staging between the S/O phases and the M computation.
__global__ __launch_bounds__(128) void attn_intraM_kernel(const float* __restrict__ order_coeff,
                                                          const float* __restrict__ qcw,
                                                          const float* __restrict__ qcb,
                                                          const float* __restrict__ kcw,
                                                          const float* __restrict__ kcb,
                                                          const float* __restrict__ vcw,
                                                          const float* __restrict__ vcb)
{
    extern __shared__ __align__(16) float sm_att[];
    float* KSs = sm_att;                   // Q staging -> K(row-major) -> weighted S
    float* Vt  = sm_att + 64 * AT_NW;      // V^T  [e][m]
    float* Kd  = sm_att + 2 * 64 * AT_NW;  // decayed K^T  [d][m]

    const int h    = blockIdx.y;
    const int lt   = blockIdx.x;
    const int l0   = lt * 64;
    const int tid  = threadIdx.x;
    const int lane = tid & 31;
    const int w    = tid >> 5;
    const int g    = lane >> 2;
    const int t4   = lane & 3;
    const int wl   = w * 16;

    const float* ca = g_ca + h * L_;
    const float lc  = __logf(1.f / order_coeff[h]);
    const float4 z = make_float4(0.f, 0.f, 0.f, 0.f);
    const bool hasM = (lt < NCH_ - 1);
    const float bnext = hasM ? ca[(lt + 1) * 64] : 0.f;

    const int c4i = (tid & 15) << 2;
    const int chq = h * 64 + c4i;

    // ---- stage Q (conv fused, tf32) into KSs ----
    {
        const float4 qwa = *reinterpret_cast<const float4*>(&qcw[2 * chq]);
        const float4 qwb = *reinterpret_cast<const float4*>(&qcw[2 * chq + 4]);
        const float4 qbb = *reinterpret_cast<const float4*>(&qcb[chq]);
#pragma unroll
        for (int it = 0; it < 8; it++) {
            const int row = (tid >> 4) + it * 8;
            const int gl = l0 + row;
            float4 qc4 = *reinterpret_cast<const float4*>(&g_qkv[(size_t)gl * T3_ + chq]);
            float4 qp4 = (gl > 0) ? *reinterpret_cast<const float4*>(&g_qkv[(size_t)(gl - 1) * T3_ + chq]) : z;
            cvt_store<AT_NW>(KSs, row, c4i, conv4(qc4, qp4, qwa, qwb, qbb));
        }
    }
    __syncthreads();

    uint32_t qa[8][4];
    {
        const uint32_t* Qu = reinterpret_cast<const uint32_t*>(KSs);
#pragma unroll
        for (int ko = 0; ko < 8; ko++) {
            qa[ko][0] = Qu[(wl + g) * AT_NW + ko * 8 + t4];
            qa[ko][1] = Qu[(wl + g + 8) * AT_NW + ko * 8 + t4];
            qa[ko][2] = Qu[(wl + g) * AT_NW + ko * 8 + t4 + 4];
            qa[ko][3] = Qu[(wl + g + 8) * AT_NW + ko * 8 + t4 + 4];
        }
    }
    const float cl0 = ca[l0 + wl + g] + lc;
    const float cl1 = ca[l0 + wl + g + 8] + lc;
    __syncthreads();

    // ---- load K (conv) into KSs row-major + decayed K^T into Kd; V^T into Vt ----
    {
        const float4 kwa = *reinterpret_cast<const float4*>(&kcw[2 * chq]);
        const float4 kwb = *reinterpret_cast<const float4*>(&kcw[2 * chq + 4]);
        const float4 kbb = *reinterpret_cast<const float4*>(&kcb[chq]);
        const float4 vwa = *reinterpret_cast<const float4*>(&vcw[2 * chq]);
        const float4 vwb = *reinterpret_cast<const float4*>(&vcw[2 * chq + 4]);
        const float4 vbb = *reinterpret_cast<const float4*>(&vcb[chq]);
#pragma unroll
        for (int it = 0; it < 8; it++) {
            const int row = (tid >> 4) + it * 8;
            const int gl = l0 + row;
            const float dtv = g_dt[h * L_ + gl];
            const float* rowp  = g_qkv + (size_t)gl * T3_;
            const float* prowp = rowp - T3_;
            const bool hasp = (gl > 0);
            float4 kc4 = *reinterpret_cast<const float4*>(&rowp[QS_ + chq]);
            float4 kp4 = hasp ? *reinterpret_cast<const float4*>(&prowp[QS_ + chq]) : z;
            float4 kx = conv4(kc4, kp4, kwa, kwb, kbb);
            cvt_store<AT_NW>(KSs, row, c4i, kx);
            if (hasM) {
                const float wm = __expf(bnext - ca[gl]);
                Kd[(c4i + 0) * AT_NW + row] = f2tf32f(kx.x * wm);
                Kd[(c4i + 1) * AT_NW + row] = f2tf32f(kx.y * wm);
                Kd[(c4i + 2) * AT_NW + row] = f2tf32f(kx.z * wm);
                Kd[(c4i + 3) * AT_NW + row] = f2tf32f(kx.w * wm);
            }

            float4 vc4 = *reinterpret_cast<const float4*>(&rowp[2 * QS_ + chq]);
            float4 vp4 = hasp ? *reinterpret_cast<const float4*>(&prowp[2 * QS_ + chq]) : z;
            float4 vx = conv4(vc4, vp4, vwa, vwb, vbb);
            Vt[(c4i + 0) * AT_NW + row] = f2tf32f(vx.x * dtv);
            Vt[(c4i + 1) * AT_NW + row] = f2tf32f(vx.y * dtv);
            Vt[(c4i + 2) * AT_NW + row] = f2tf32f(vx.z * dtv);
            Vt[(c4i + 3) * AT_NW + row] = f2tf32f(vx.w * dtv);
        }
    }
    __syncthreads();

    // ---- M-phase (same fragment/MMA order as old kv_outer -> bit-identical) ----
    if (hasM) {
        float macc[8][4];
#pragma unroll
        for (int nt = 0; nt < 8; nt++)
#pragma unroll
            for (int e = 0; e < 4; e++) macc[nt][e] = 0.f;

        const uint32_t* Vu = reinterpret_cast<const uint32_t*>(Vt);
        const uint32_t* Ku = reinterpret_cast<const uint32_t*>(Kd);
#pragma unroll
        for (int ko = 0; ko < 8; ko++) {
            uint32_t a[4];
            a[0] = Vu[(wl + g) * AT_NW + ko * 8 + t4];
            a[1] = Vu[(wl + g + 8) * AT_NW + ko * 8 + t4];
            a[2] = Vu[(wl + g) * AT_NW + ko * 8 + t4 + 4];
            a[3] = Vu[(wl + g + 8) * AT_NW + ko * 8 + t4 + 4];
#pragma unroll
            for (int nt = 0; nt < 8; nt++) {
                uint32_t b[2];
                b[0] = Ku[(nt * 8 + g) * AT_NW + ko * 8 + t4];
                b[1] = Ku[(nt * 8 + g) * AT_NW + ko * 8 + t4 + 4];
                MMA_TF32(macc[nt], a, b);
            }
        }

        float* Md = g_M + ((size_t)(h * NCH_ + lt) << 12);
#pragma unroll
        for (int nt = 0; nt < 8; nt++) {
            const int dc = nt * 8 + 2 * t4;
            *reinterpret_cast<float2*>(&Md[(wl + g) * 64 + dc])     = make_float2(macc[nt][0], macc[nt][1]);
            *reinterpret_cast<float2*>(&Md[(wl + g + 8) * 64 + dc]) = make_float2(macc[nt][2], macc[nt][3]);
        }
    }

    // ---- S-phase: sfr = Q(16x64) . K^T(64x64) ----
    float sfr[8][4];
#pragma unroll
    for (int nt = 0; nt < 8; nt++)
#pragma unroll
        for (int e = 0; e < 4; e++) sfr[nt][e] = 0.f;

    {
        const uint32_t* Ku = reinterpret_cast<const uint32_t*>(KSs);
#pragma unroll
        for (int ko = 0; ko < 8; ko++) {
            uint32_t b[8][2];
#pragma unroll
            for (int nt = 0; nt < 8; nt++) {
                b[nt][0] = Ku[(nt * 8 + g) * AT_NW + ko * 8 + t4];
                b[nt][1] = Ku[(nt * 8 + g) * AT_NW + ko * 8 + t4 + 4];
            }
#pragma unroll
            for (int nt = 0; nt < 8; nt++)
                MMA_TF32(sfr[nt], qa[ko], b[nt]);
        }
    }

    const int gl0 = l0 + wl + g, gl1 = gl0 + 8;
#pragma unroll
    for (int nt = 0; nt < 8; nt++) {
        const int gm0 = l0 + nt * 8 + 2 * t4;
        const int gm1 = gm0 + 1;
        const float cm0 = ca[gm0], cm1 = ca[gm1];
        sfr[nt][0] *= (gm0 <= gl0) ? __expf(cl0 - cm0) : 0.f;
        sfr[nt][1] *= (gm1 <= gl0) ? __expf(cl0 - cm1) : 0.f;
        sfr[nt][2] *= (gm0 <= gl1) ? __expf(cl1 - cm0) : 0.f;
        sfr[nt][3] *= (gm1 <= gl1) ? __expf(cl1 - cm1) : 0.f;
    }
    __syncthreads();

#pragma unroll
    for (int nt = 0; nt < 8; nt++) {
        const int cc = nt * 8 + 2 * t4;
        *reinterpret_cast<float2*>(&KSs[(wl + g) * AT_NW + cc]) =
            make_float2(f2tf32f(sfr[nt][0]), f2tf32f(sfr[nt][1]));
        *reinterpret_cast<float2*>(&KSs[(wl + g + 8) * AT_NW + cc]) =
            make_float2(f2tf32f(sfr[nt][2]), f2tf32f(sfr[nt][3]));
    }
    __syncwarp();

    float accO[8][4];
#pragma unroll
    for (int nt = 0; nt < 8; nt++)
#pragma unroll
        for (int e = 0; e < 4; e++) accO[nt][e] = 0.f;

    {
        const uint32_t* Su = reinterpret_cast<const uint32_t*>(KSs);
        const uint32_t* Vu = reinterpret_cast<const uint32_t*>(Vt);
#pragma unroll
        for (int ko = 0; ko < 8; ko++) {
            uint32_t a[4];
            a[0] = Su[(wl + g) * AT_NW + ko * 8 + t4];
            a[1] = Su[(wl + g + 8) * AT_NW + ko * 8 + t4];
            a[2] = Su[(wl + g) * AT_NW + ko * 8 + t4 + 4];
            a[3] = Su[(wl + g + 8) * AT_NW + ko * 8 + t4 + 4];
#pragma unroll
            for (int nt = 0; nt < 8; nt++) {
                uint32_t b[2];
                b[0] = Vu[(nt * 8 + g) * AT_NW + ko * 8 + t4];
                b[1] = Vu[(nt * 8 + g) * AT_NW + ko * 8 + t4 + 4];
                MMA_TF32(accO[nt], a, b);
            }
        }
    }

    // write pre-RMS partial
#pragma unroll
    for (int nt = 0; nt < 8; nt++) {
        const int dc = nt * 8 + 2 * t4;
        const int col = h * DH_ + dc;
        *reinterpret_cast<float2*>(&g_pacc[(size_t)(l0 + wl + g) * QS_ + col]) =
            make_float2(accO[nt][0], accO[nt][1]);
        *reinterpret_cast<float2*>(&g_pacc[(size_t)(l0 + wl + g + 8) * QS_ + col]) =
            make_float2(accO[nt][2], accO[nt][3]);
    }
}

// ---- Phase B: per-head state scan, depth-2 register prefetch. grid H, 1024 thr --
__global__ __launch_bounds__(1024) void state_scan_kernel()
{
    const int h = blockIdx.x, t = threadIdx.x;
    __shared__ float decs[NCH_];
    if (t < NCH_) {
        const float* ca = g_ca + h * L_;
        decs[t] = (t < NCH_ - 1) ? __expf(ca[(t + 1) * 64] - ca[t * 64]) : 0.f;
    }
    __syncthreads();

    const float* Mbase = g_M + ((size_t)h * NCH_ << 12);
    float* Sbase = g_state + ((size_t)h * NCH_ << 12);
    const int off = t * 4;

    float4 st = make_float4(0.f, 0.f, 0.f, 0.f);
    float4 mbuf0 = *reinterpret_cast<const float4*>(&Mbase[off]);
    float4 mbuf1 = *reinterpret_cast<const float4*>(&Mbase[(1 << 12) + off]);

    for (int c = 0; c < NCH_; c++) {
        *reinterpret_cast<float4*>(&Sbase[((size_t)c << 12) + off]) = st;
        if (c < NCH_ - 1) {
            const float dec = decs[c];
            st.x = fmaf(st.x, dec, mbuf0.x);
            st.y = fmaf(st.y, dec, mbuf0.y);
            st.z = fmaf(st.z, dec, mbuf0.z);
            st.w = fmaf(st.w, dec, mbuf0.w);
            mbuf0 = mbuf1;
            if (c + 2 < NCH_)
                mbuf1 = *reinterpret_cast<const float4*>(&Mbase[((size_t)(c + 2) << 12) + off]);
        }
    }
}

// ---- Inter: P = Q.State^T * iw + partial, RMSNorm, write g_attn -----------------
__global__ __launch_bounds__(128) void attn_inter_kernel(const float* __restrict__ norm_w,
                                                         const float* __restrict__ order_coeff,
                                                         const float* __restrict__ qcw,
                                                         const float* __restrict__ qcb)
{
    __shared__ __align__(16) float Qs[64 * AT_NW];
    __shared__ __align__(16) float St[64 * AT_NW];

    const int h    = blockIdx.y;
    const int lt   = blockIdx.x;
    const int l0   = lt * 64;
    const int tid  = threadIdx.x;
    const int lane = tid & 31;
    const int w    = tid >> 5;
    const int g    = lane >> 2;
    const int t4   = lane & 3;
    const int wl   = w * 16;

    const float* ca = g_ca + h * L_;
    const float lc  = __logf(1.f / order_coeff[h]);
    const float4 z = make_float4(0.f, 0.f, 0.f, 0.f);

    const int c4i = (tid & 15) << 2;
    const int chq = h * 64 + c4i;

    {
        const float4 qwa = *reinterpret_cast<const float4*>(&qcw[2 * chq]);
        const float4 qwb = *reinterpret_cast<const float4*>(&qcw[2 * chq + 4]);
        const float4 qbb = *reinterpret_cast<const float4*>(&qcb[chq]);
        const float* Sg = g_state + ((size_t)(h * NCH_ + lt) << 12);
#pragma unroll
        for (int it = 0; it < 8; it++) {
            const int row = (tid >> 4) + it * 8;
            const int gl = l0 + row;
            float4 qc4 = *reinterpret_cast<const float4*>(&g_qkv[(size_t)gl * T3_ + chq]);
            float4 qp4 = (gl > 0) ? *reinterpret_cast<const float4*>(&g_qkv[(size_t)(gl - 1) * T3_ + chq]) : z;
            cvt_store<AT_NW>(Qs, row, c4i, conv4(qc4, qp4, qwa, qwb, qbb));
            cvt_store<AT_NW>(St, row, c4i,
                *reinterpret_cast<const float4*>(&Sg[row * 64 + c4i]));
        }
    }
    __syncthreads();

    uint32_t qa[8][4];
    {
        const uint32_t* Qu = reinterpret_cast<const uint32_t*>(Qs);
#pragma unroll
        for (int ko = 0; ko < 8; ko++) {
            qa[ko][0] = Qu[(wl + g) * AT_NW + ko * 8 + t4];
            qa[ko][1] = Qu[(wl + g + 8) * AT_NW + ko * 8 + t4];
            qa[ko][2] = Qu[(wl + g) * AT_NW + ko * 8 + t4 + 4];
            qa[ko][3] = Qu[(wl + g + 8) * AT_NW + ko * 8 + t4 + 4];
        }
    }
    const float cl0 = ca[l0 + wl + g] + lc;
    const float cl1 = ca[l0 + wl + g + 8] + lc;
    const float bc  = ca[l0];
    const float iw0 = __expf(cl0 - bc);
    const float iw1 = __expf(cl1 - bc);

    float accO[8][4];
#pragma unroll
    for (int nt = 0; nt < 8; nt++)
#pragma unroll
        for (int e = 0; e < 4; e++) accO[nt][e] = 0.f;

    {
        const uint32_t* Su = reinterpret_cast<const uint32_t*>(St);
#pragma unroll
        for (int ko = 0; ko < 8; ko++) {
            uint32_t b[8][2];
#pragma unroll
            for (int nt = 0; nt < 8; nt++) {
                b[nt][0] = Su[(nt * 8 + g) * AT_NW + ko * 8 + t4];
                b[nt][1] = Su[(nt * 8 + g) * AT_NW + ko * 8 + t4 + 4];
            }
#pragma unroll
            for (int nt = 0; nt < 8; nt++)
                MMA_TF32(accO[nt], qa[ko], b[nt]);
        }
    }

#pragma unroll
    for (int nt = 0; nt < 8; nt++) {
        const int dc = nt * 8 + 2 * t4;
        const int col = h * DH_ + dc;
        const float2 p0 = *reinterpret_cast<const float2*>(&g_pacc[(size_t)(l0 + wl + g) * QS_ + col]);
        const float2 p1 = *reinterpret_cast<const float2*>(&g_pacc[(size_t)(l0 + wl + g + 8) * QS_ + col]);
        accO[nt][0] = fmaf(accO[nt][0], iw0, p0.x);
        accO[nt][1] = fmaf(accO[nt][1], iw0, p0.y);
        accO[nt][2] = fmaf(accO[nt][2], iw1, p1.x);
        accO[nt][3] = fmaf(accO[nt][3], iw1, p1.y);
    }

    float ss0 = 0.f, ss1 = 0.f;
#pragma unroll
    for (int nt = 0; nt < 8; nt++) {
        ss0 = fmaf(accO[nt][0], accO[nt][0], ss0);
        ss0 = fmaf(accO[nt][1], accO[nt][1], ss0);
        ss1 = fmaf(accO[nt][2], accO[nt][2], ss1);
        ss1 = fmaf(accO[nt][3], accO[nt][3], ss1);
    }
    ss0 += __shfl_xor_sync(0xffffffffu, ss0, 1);
    ss0 += __shfl_xor_sync(0xffffffffu, ss0, 2);
    ss1 += __shfl_xor_sync(0xffffffffu, ss1, 1);
    ss1 += __shfl_xor_sync(0xffffffffu, ss1, 2);
    const float r0 = rsqrtf(ss0 * (1.f / 64.f) + EPS_);
    const float r1 = rsqrtf(ss1 * (1.f / 64.f) + EPS_);

#pragma unroll
    for (int nt = 0; nt < 8; nt++) {
        const int dc = nt * 8 + 2 * t4;
        const float2 nw = *reinterpret_cast<const float2*>(&norm_w[dc]);
        const int col = h * DH_ + dc;
        *reinterpret_cast<float2*>(&g_attn[(size_t)(l0 + wl + g) * QS_ + col]) =
            make_float2(accO[nt][0] * r0 * nw.x, accO[nt][1] * r0 * nw.y);
        *reinterpret_cast<float2*>(&g_attn[(size_t)(l0 + wl + g + 8) * QS_ + col]) =
            make_float2(accO[nt][2] * r1 * nw.x, accO[nt][3] * r1 * nw.y);
    }
}

// ---------------- launch ---------------------------------------------------------
#define GEMM_SMEM_QKV ((128 + 96) * 36 * 2 * (int)sizeof(float))   // 64512 bytes
#define GEMM_SMEM_O   ((128 + 64) * 36 * 2 * (int)sizeof(float))   // 55296 bytes

extern "C" void kernel_launch(void* const* d_in, const int* in_sizes, int n_in,
                              void* d_out, int out_size)
{
    const float* hidden    = (const float*)d_in[0];
    // d_in[1] = attention_mask (causal triu) — structurally known, unused
    const float* qkv_w     = (const float*)d_in[2];
    const float* q_conv_w  = (const float*)d_in[3];
    const float* q_conv_b  = (const float*)d_in[4];
    const float* k_conv_w  = (const float*)d_in[5];
    const float* k_conv_b  = (const float*)d_in[6];
    const float* v_conv_w  = (const float*)d_in[7];
    const float* v_conv_b  = (const float*)d_in[8];
    const float* norm_w    = (const float*)d_in[9];
    const float* A_log     = (const float*)d_in[10];
    const float* dt_bias   = (const float*)d_in[11];
    const float* dt_proj_w = (const float*)d_in[12];
    const float* dt_proj_b = (const float*)d_in[13];
    const float* o_w       = (const float*)d_in[14];
    const float* order_c   = (const float*)d_in[15];
    float* out = (float*)d_out;

    static int init_done = 0;
    static cudaStream_t s2;
    static cudaEvent_t ev_fork, ev_dt;
    if (!init_done) {
        cudaFuncSetAttribute(mma_qkv_kernel, cudaFuncAttributeMaxDynamicSharedMemorySize, GEMM_SMEM_QKV);
        cudaFuncSetAttribute(mma_o_kernel,   cudaFuncAttributeMaxDynamicSharedMemorySize, GEMM_SMEM_O);
        cudaFuncSetAttribute(attn_intraM_kernel, cudaFuncAttributeMaxDynamicSharedMemorySize, ATTN_SMEM);
        cudaStreamCreateWithFlags(&s2, cudaStreamNonBlocking);
        cudaEventCreateWithFlags(&ev_fork, cudaEventDisableTiming);
        cudaEventCreateWithFlags(&ev_dt,   cudaEventDisableTiming);
        init_done = 1;
    }

    // fork: dt + cumsum (depend only on hidden) concurrent with the qkv GEMM
    cudaEventRecord(ev_fork, 0);
    cudaStreamWaitEvent(s2, ev_fork, 0);
    dt_kernel<<<L_ / 8, 512, 0, s2>>>(hidden, dt_proj_w, dt_proj_b, dt_bias, A_log);
    cumsum_kernel<<<H_, 256, 0, s2>>>();
    cudaEventRecord(ev_dt, s2);

    mma_qkv_kernel<<<dim3(T3_ / 96, L_ / 128), 256, GEMM_SMEM_QKV>>>(hidden, qkv_w);

    // join: fused kernel needs qkv + dt/ca
    cudaStreamWaitEvent(0, ev_dt, 0);
    attn_intraM_kernel<<<dim3(NCH_, H_), 128, ATTN_SMEM>>>(order_c,
                                                           q_conv_w, q_conv_b,
                                                           k_conv_w, k_conv_b,
                                                           v_conv_w, v_conv_b);
    state_scan_kernel<<<H_, 1024>>>();
    attn_inter_kernel<<<dim3(NCH_, H_), 128>>>(norm_w, order_c, q_conv_w, q_conv_b);
    mma_o_kernel<<<dim3(HID_ / 64, L_ / 128), 256, GEMM_SMEM_O>>>(o_w, out);
}